// round 12
// baseline (speedup 1.0000x reference)
#include <cuda_runtime.h>
#include <math.h>

// Packed accumulator: bits [44:) = block counter, bits [0:44) = biased
// fixed-point (2^20) cosine sum. Last block writes out + resets -> replay-safe.
__device__ unsigned long long g_acc = 0ULL;

#define FIX_ONE   (1048576.0f)            // 2^20
#define BIAS      (1LL << 24)
#define CNT_SHIFT 44
#define SUM_MASK  ((1ULL << CNT_SHIFT) - 1ULL)

// --- Single fused kernel: 2 samples per warp, 16 batched float4 loads. ----
__global__ __launch_bounds__(256, 2) void cos_main(
    const float* __restrict__ emb,
    const void*  __restrict__ labels_raw,
    const float* __restrict__ protos,
    float* __restrict__ out,
    int B, int D, int C)
{
    const int wib  = threadIdx.x >> 5;
    const int lane = threadIdx.x & 31;
    const int warp = blockIdx.x * 8 + wib;      // warp id; handles samples 2w, 2w+1

    // Per-warp label dtype detection (32B L2-hot broadcast; P(miss) ~ 1e-16).
    const long long* l64 = (const long long*)labels_raw;
    bool is64;
    {
        int nq = B >= 8 ? 4 : (B >= 2 ? B / 2 : 0);
        bool ok = (nq > 0);
        for (int i = 0; i < nq; i++) {
            unsigned long long v = (unsigned long long)l64[i];
            ok &= (v < (unsigned long long)C);
        }
        is64 = ok;
    }

    const int s0 = warp * 2;
    const int s1 = s0 + 1;
    const bool v0 = (s0 < B);
    const bool v1 = (s1 < B);

    float cos01 = 0.f;   // cos(s0) + cos(s1), valid on lane 0 after reduction

    if (D == 512) {
        // Labels first (both), then ALL 16 data loads, then math.
        long long lab0 = 0, lab1 = 0;
        if (v0) {
            lab0 = is64 ? l64[s0] : (long long)((const int*)labels_raw)[s0];
            if (lab0 < 0) lab0 = 0;
            if (lab0 >= (long long)C) lab0 = C - 1;
        }
        if (v1) {
            lab1 = is64 ? l64[s1] : (long long)((const int*)labels_raw)[s1];
            if (lab1 < 0) lab1 = 0;
            if (lab1 >= (long long)C) lab1 = C - 1;
        }

        const float4* e0 = reinterpret_cast<const float4*>(emb + (size_t)s0 * 512);
        const float4* e1 = reinterpret_cast<const float4*>(emb + (size_t)s1 * 512);
        const float4* p0 = reinterpret_cast<const float4*>(protos + (size_t)lab0 * 512);
        const float4* p1 = reinterpret_cast<const float4*>(protos + (size_t)lab1 * 512);

        float4 ea[4], pa[4], eb[4], pb[4];
        const float4 z = make_float4(0.f, 0.f, 0.f, 0.f);
        #pragma unroll
        for (int k = 0; k < 4; k++) ea[k] = v0 ? e0[lane + 32 * k] : z;
        #pragma unroll
        for (int k = 0; k < 4; k++) eb[k] = v1 ? e1[lane + 32 * k] : z;
        #pragma unroll
        for (int k = 0; k < 4; k++) pa[k] = v0 ? p0[lane + 32 * k] : z;
        #pragma unroll
        for (int k = 0; k < 4; k++) pb[k] = v1 ? p1[lane + 32 * k] : z;

        float dep0 = 0.f, dee0 = 0.f, dpp0 = 0.f;
        float dep1 = 0.f, dee1 = 0.f, dpp1 = 0.f;
        #pragma unroll
        for (int k = 0; k < 4; k++) {
            dep0 = fmaf(ea[k].x, pa[k].x, fmaf(ea[k].y, pa[k].y,
                   fmaf(ea[k].z, pa[k].z, fmaf(ea[k].w, pa[k].w, dep0))));
            dee0 = fmaf(ea[k].x, ea[k].x, fmaf(ea[k].y, ea[k].y,
                   fmaf(ea[k].z, ea[k].z, fmaf(ea[k].w, ea[k].w, dee0))));
            dpp0 = fmaf(pa[k].x, pa[k].x, fmaf(pa[k].y, pa[k].y,
                   fmaf(pa[k].z, pa[k].z, fmaf(pa[k].w, pa[k].w, dpp0))));
            dep1 = fmaf(eb[k].x, pb[k].x, fmaf(eb[k].y, pb[k].y,
                   fmaf(eb[k].z, pb[k].z, fmaf(eb[k].w, pb[k].w, dep1))));
            dee1 = fmaf(eb[k].x, eb[k].x, fmaf(eb[k].y, eb[k].y,
                   fmaf(eb[k].z, eb[k].z, fmaf(eb[k].w, eb[k].w, dee1))));
            dpp1 = fmaf(pb[k].x, pb[k].x, fmaf(pb[k].y, pb[k].y,
                   fmaf(pb[k].z, pb[k].z, fmaf(pb[k].w, pb[k].w, dpp1))));
        }

        #pragma unroll
        for (int off = 16; off > 0; off >>= 1) {
            dep0 += __shfl_xor_sync(0xFFFFFFFFu, dep0, off);
            dee0 += __shfl_xor_sync(0xFFFFFFFFu, dee0, off);
            dpp0 += __shfl_xor_sync(0xFFFFFFFFu, dpp0, off);
            dep1 += __shfl_xor_sync(0xFFFFFFFFu, dep1, off);
            dee1 += __shfl_xor_sync(0xFFFFFFFFu, dee1, off);
            dpp1 += __shfl_xor_sync(0xFFFFFFFFu, dpp1, off);
        }

        if (lane == 0) {
            if (v0) cos01 += dep0 / (fmaxf(sqrtf(dee0), 1e-8f) * fmaxf(sqrtf(dpp0), 1e-8f));
            if (v1) cos01 += dep1 / (fmaxf(sqrtf(dee1), 1e-8f) * fmaxf(sqrtf(dpp1), 1e-8f));
        }
    } else {
        // Generic path: one sample at a time.
        for (int t = 0; t < 2; t++) {
            int s = s0 + t;
            float dep = 0.f, dee = 0.f, dpp = 0.f;
            if (s < B) {
                long long lab = is64 ? l64[s] : (long long)((const int*)labels_raw)[s];
                if (lab < 0) lab = 0;
                if (lab >= (long long)C) lab = C - 1;
                const float* e = emb + (size_t)s * D;
                const float* p = protos + (size_t)lab * D;
                for (int i = lane; i < D; i += 32) {
                    float evs = e[i], pvs = p[i];
                    dep = fmaf(evs, pvs, dep);
                    dee = fmaf(evs, evs, dee);
                    dpp = fmaf(pvs, pvs, dpp);
                }
            }
            #pragma unroll
            for (int off = 16; off > 0; off >>= 1) {
                dep += __shfl_xor_sync(0xFFFFFFFFu, dep, off);
                dee += __shfl_xor_sync(0xFFFFFFFFu, dee, off);
                dpp += __shfl_xor_sync(0xFFFFFFFFu, dpp, off);
            }
            if (lane == 0 && s < B)
                cos01 += dep / (fmaxf(sqrtf(dee), 1e-8f) * fmaxf(sqrtf(dpp), 1e-8f));
        }
    }

    __shared__ float s_cos[8];
    if (lane == 0) s_cos[wib] = cos01;
    __syncthreads();

    if (threadIdx.x == 0) {
        float acc = 0.f;
        #pragma unroll
        for (int w = 0; w < 8; w++) acc += s_cos[w];

        // |acc| <= 16 -> biased fixed-point always positive, no carry into cnt.
        long long fixed = __float2ll_rn(acc * FIX_ONE) + BIAS;
        unsigned long long add = (1ULL << CNT_SHIFT) | (unsigned long long)fixed;
        unsigned long long old = atomicAdd(&g_acc, add);

        if ((unsigned)(old >> CNT_SHIFT) == (unsigned)(gridDim.x - 1)) {
            unsigned long long total = old + add;
            long long fixsum = (long long)(total & SUM_MASK)
                             - (long long)gridDim.x * BIAS;
            double sum = (double)fixsum / (double)FIX_ONE;
            out[0] = 1.0f - (float)(sum / (double)B);
            atomicExch(&g_acc, 0ULL);          // reset for next graph replay
        }
    }
}

extern "C" void kernel_launch(void* const* d_in, const int* in_sizes, int n_in,
                              void* d_out, int out_size)
{
    // metadata order: embeddings [B*D] f32, labels [B], prototypes [C*D] f32
    const float* emb    = (const float*)d_in[0];
    const void*  labels = d_in[1];
    const float* protos = (const float*)d_in[2];
    float*       out    = (float*)d_out;

    const int B = in_sizes[1];
    const int D = in_sizes[0] / B;
    const int C = in_sizes[2] / D;

    int blocks = (B + 15) / 16;                // 8 warps x 2 samples per block

    cos_main<<<blocks, 256>>>(emb, labels, protos, out, B, D, C);
}

// round 13
// speedup vs baseline: 1.1790x; 1.1790x over previous
#include <cuda_runtime.h>
#include <math.h>

// Packed accumulator: bits [44:) = block counter, bits [0:44) = biased
// fixed-point (2^20) cosine sum. Last block writes out + resets -> replay-safe.
__device__ unsigned long long g_acc = 0ULL;

#define FIX_ONE   (1048576.0f)            // 2^20
#define BIAS      (1LL << 24)
#define CNT_SHIFT 44
#define SUM_MASK  ((1ULL << CNT_SHIFT) - 1ULL)

// --- Single fused kernel: warp-per-sample; label -> 4 emb loads -> 4 proto
//     loads fully batched (MLP=8), then FMAs. Packed-atomic finish. ---------
__global__ __launch_bounds__(256) void cos_main(
    const float* __restrict__ emb,
    const void*  __restrict__ labels_raw,
    const float* __restrict__ protos,
    float* __restrict__ out,
    int B, int D, int C)
{
    const int wib  = threadIdx.x >> 5;
    const int lane = threadIdx.x & 31;
    const int warp = blockIdx.x * 8 + wib;

    // Per-warp label dtype detection (32B L2-hot broadcast; P(miss) ~ 1e-16).
    const long long* l64 = (const long long*)labels_raw;
    bool is64;
    {
        int nq = B >= 8 ? 4 : (B >= 2 ? B / 2 : 0);
        bool ok = (nq > 0);
        for (int i = 0; i < nq; i++) {
            unsigned long long v = (unsigned long long)l64[i];
            ok &= (v < (unsigned long long)C);
        }
        is64 = ok;
    }

    float dep = 0.f, dee = 0.f, dpp = 0.f;

    if (warp < B) {
        // 1. Label first (its latency is covered by the emb loads below).
        long long lab;
        if (is64) lab = l64[warp];
        else      lab = (long long)((const int*)labels_raw)[warp];
        if (lab < 0) lab = 0;
        if (lab >= (long long)C) lab = C - 1;

        if (D == 512) {
            const float4* e = reinterpret_cast<const float4*>(emb + (size_t)warp * 512);
            const float4* p = reinterpret_cast<const float4*>(protos + (size_t)lab * 512);

            // 2. Four independent embedding loads (no label dependency).
            float4 ev[4];
            #pragma unroll
            for (int k = 0; k < 4; k++) ev[k] = e[lane + 32 * k];

            // 3. Four prototype loads (depend on label, now resolved).
            float4 pv[4];
            #pragma unroll
            for (int k = 0; k < 4; k++) pv[k] = p[lane + 32 * k];

            // 4. Math only after all 8 loads are in flight.
            #pragma unroll
            for (int k = 0; k < 4; k++) {
                dep = fmaf(ev[k].x, pv[k].x, fmaf(ev[k].y, pv[k].y,
                      fmaf(ev[k].z, pv[k].z, fmaf(ev[k].w, pv[k].w, dep))));
                dee = fmaf(ev[k].x, ev[k].x, fmaf(ev[k].y, ev[k].y,
                      fmaf(ev[k].z, ev[k].z, fmaf(ev[k].w, ev[k].w, dee))));
                dpp = fmaf(pv[k].x, pv[k].x, fmaf(pv[k].y, pv[k].y,
                      fmaf(pv[k].z, pv[k].z, fmaf(pv[k].w, pv[k].w, dpp))));
            }
        } else {
            const float* e = emb + (size_t)warp * D;
            const float* p = protos + (size_t)lab * D;
            for (int i = lane; i < D; i += 32) {
                float evs = e[i], pvs = p[i];
                dep = fmaf(evs, pvs, dep);
                dee = fmaf(evs, evs, dee);
                dpp = fmaf(pvs, pvs, dpp);
            }
        }
    }

    #pragma unroll
    for (int off = 16; off > 0; off >>= 1) {
        dep += __shfl_xor_sync(0xFFFFFFFFu, dep, off);
        dee += __shfl_xor_sync(0xFFFFFFFFu, dee, off);
        dpp += __shfl_xor_sync(0xFFFFFFFFu, dpp, off);
    }

    __shared__ float s_cos[8];
    if (lane == 0) {
        float cosv = 0.f;
        if (warp < B) {
            float en = fmaxf(sqrtf(dee), 1e-8f);
            float pn = fmaxf(sqrtf(dpp), 1e-8f);
            cosv = dep / (en * pn);
        }
        s_cos[wib] = cosv;
    }
    __syncthreads();

    if (threadIdx.x == 0) {
        float acc = 0.f;
        #pragma unroll
        for (int w = 0; w < 8; w++) acc += s_cos[w];

        // |acc| <= 8 -> biased fixed-point always positive, no carry into cnt.
        long long fixed = __float2ll_rn(acc * FIX_ONE) + BIAS;
        unsigned long long add = (1ULL << CNT_SHIFT) | (unsigned long long)fixed;
        unsigned long long old = atomicAdd(&g_acc, add);

        if ((unsigned)(old >> CNT_SHIFT) == (unsigned)(gridDim.x - 1)) {
            unsigned long long total = old + add;
            long long fixsum = (long long)(total & SUM_MASK)
                             - (long long)gridDim.x * BIAS;
            double sum = (double)fixsum / (double)FIX_ONE;
            out[0] = 1.0f - (float)(sum / (double)B);
            atomicExch(&g_acc, 0ULL);          // reset for next graph replay
        }
    }
}

extern "C" void kernel_launch(void* const* d_in, const int* in_sizes, int n_in,
                              void* d_out, int out_size)
{
    // metadata order: embeddings [B*D] f32, labels [B], prototypes [C*D] f32
    const float* emb    = (const float*)d_in[0];
    const void*  labels = d_in[1];
    const float* protos = (const float*)d_in[2];
    float*       out    = (float*)d_out;

    const int B = in_sizes[1];
    const int D = in_sizes[0] / B;
    const int C = in_sizes[2] / D;

    int blocks = (B + 7) / 8;                  // 8 warps (samples) per block

    cos_main<<<blocks, 256>>>(emb, labels, protos, out, B, D, C);
}